// round 6
// baseline (speedup 1.0000x reference)
#include <cuda_runtime.h>
#include <cstdint>

// out = concat(adj_t @ x, adj_t2 @ x), N=8192, D=256, fp32 via tf32 mma.sync.
// R6: fused CTA (both matmuls, shared B tile) + 512 threads / 16 warps
// (4 warps per SMSP) so fragment-LDS bursts of one warp overlap MMA bursts
// of another instead of phase-serializing.

constexpr int NN = 8192;
constexpr int DD = 256;
constexpr int BM = 64;
constexpr int BK = 32;
constexpr int NITER = NN / BK;            // 256
constexpr int ASTRIDE = 36;               // conflict-free A row stride
constexpr int BSTRIDE = 264;              // conflict-free B row stride
constexpr int A_ELE = BM * ASTRIDE;       // 2304 floats per matrix
constexpr int B_ELE = BK * BSTRIDE;       // 8448 floats
constexpr int STG_FLT = 2 * A_ELE + B_ELE;   // 13056
constexpr int SMEM_BYTES = 2 * STG_FLT * 4;  // 104448

__device__ float g_xt[(size_t)NN * DD];   // x pre-converted to tf32 (rna)

#define CP_ASYNC16(dst, src) \
    asm volatile("cp.async.cg.shared.global [%0], [%1], 16;" :: "r"(dst), "l"(src))

__device__ __forceinline__ uint32_t smem_u32(const void* p) {
    uint32_t a;
    asm("{ .reg .u64 t; cvta.to.shared.u64 t, %1; cvt.u32.u64 %0, t; }"
        : "=r"(a) : "l"(p));
    return a;
}

__device__ __forceinline__ void mma_tf32(float c[4], const uint32_t a[4],
                                         const uint32_t b0, const uint32_t b1) {
    asm volatile(
        "mma.sync.aligned.m16n8k8.row.col.f32.tf32.tf32.f32 "
        "{%0,%1,%2,%3}, {%4,%5,%6,%7}, {%8,%9}, {%0,%1,%2,%3};"
        : "+f"(c[0]), "+f"(c[1]), "+f"(c[2]), "+f"(c[3])
        : "r"(a[0]), "r"(a[1]), "r"(a[2]), "r"(a[3]), "r"(b0), "r"(b1));
}

__global__ void xprep(const float* __restrict__ x) {
    const int i = blockIdx.x * 256 + threadIdx.x;
    float v = x[i];
    uint32_t t;
    asm("cvt.rna.tf32.f32 %0, %1;" : "=r"(t) : "f"(v));
    g_xt[i] = __uint_as_float(t);
}

__global__ void __launch_bounds__(512, 1) h2gcn_mma(
    const float* __restrict__ adj1,
    const float* __restrict__ adj2,
    float* __restrict__ out)
{
    extern __shared__ float smf[];
    const uint32_t smb = smem_u32(smf);

    const int t    = threadIdx.x;
    const int wid  = t >> 5;
    const int lane = t & 31;
    const int m0   = blockIdx.x * BM;

    const int wm  = wid & 3;     // 4 warp rows (16 M each)
    const int wn  = wid >> 2;    // 4 warp cols (64 N each)
    const int gid = lane >> 2;
    const int tig = lane & 3;

    // ---- cp.async assignments (512 threads) ----
    // A1: 512 16B-chunks -> 1/thread; A2: 1/thread; B: 2048 -> 4/thread
    const char* a1ptr; const char* a2ptr; uint32_t adst0;
    {
        int row = t >> 3;            // 0..63
        int c   = t & 7;
        a1ptr = reinterpret_cast<const char*>(adj1 + (size_t)(m0 + row) * NN) + c * 16;
        a2ptr = reinterpret_cast<const char*>(adj2 + (size_t)(m0 + row) * NN) + c * 16;
        adst0 = (uint32_t)((row * ASTRIDE + c * 4) * 4);
    }
    const char* bptr[4];
    uint32_t    bdst[4];
#pragma unroll
    for (int j = 0; j < 4; j++) {
        int id  = t + 512 * j;
        int row = id >> 6;           // k in tile (0..31)
        int c   = id & 63;
        bptr[j] = reinterpret_cast<const char*>(g_xt + (size_t)row * DD) + c * 16;
        bdst[j] = (uint32_t)((2 * A_ELE + row * BSTRIDE + c * 4) * 4);
    }

    auto load_stage = [&](int buf) {
        const uint32_t sb = smb + (uint32_t)(buf * STG_FLT * 4);
        CP_ASYNC16(sb + adst0, a1ptr);              a1ptr += BK * 4;
        CP_ASYNC16(sb + A_ELE * 4 + adst0, a2ptr);  a2ptr += BK * 4;
#pragma unroll
        for (int j = 0; j < 4; j++) {
            CP_ASYNC16(sb + bdst[j], bptr[j]);
            bptr[j] += (size_t)BK * DD * 4;
        }
        asm volatile("cp.async.commit_group;");
    };

    float acc[2][8][4];    // [mat][nt][i] — warp covers 16 M rows
#pragma unroll
    for (int g = 0; g < 2; g++)
#pragma unroll
        for (int nt = 0; nt < 8; nt++)
#pragma unroll
            for (int i = 0; i < 4; i++) acc[g][nt][i] = 0.0f;

    const int ar0 = (wm * 16 + gid) * ASTRIDE + tig;   // A frag base (row gid, gid+8)
    const int bc0 = wn * 64 + gid;                      // B frag column base

    load_stage(0);

    for (int it = 0; it < NITER; it++) {
        asm volatile("cp.async.wait_group 0;");
        __syncthreads();
        if (it + 1 < NITER) load_stage((it + 1) & 1);

        const float* sA1 = smf + (it & 1) * STG_FLT;
        const float* sA2 = sA1 + A_ELE;
        const float* sB  = sA1 + 2 * A_ELE;

#pragma unroll
        for (int ks = 0; ks < 4; ks++) {
            const int k = ks * 8;
            uint32_t b0[8], b1[8];
#pragma unroll
            for (int nt = 0; nt < 8; nt++) {
                const int n = bc0 + nt * 8;
                b0[nt] = __float_as_uint(sB[(k + tig) * BSTRIDE + n]);
                b1[nt] = __float_as_uint(sB[(k + tig + 4) * BSTRIDE + n]);
            }
            uint32_t a[2][4];
            {
                const int r = ar0 + k;
                a[0][0] = __float_as_uint(sA1[r]);
                a[0][1] = __float_as_uint(sA1[r + 8 * ASTRIDE]);
                a[0][2] = __float_as_uint(sA1[r + 4]);
                a[0][3] = __float_as_uint(sA1[r + 8 * ASTRIDE + 4]);
                a[1][0] = __float_as_uint(sA2[r]);
                a[1][1] = __float_as_uint(sA2[r + 8 * ASTRIDE]);
                a[1][2] = __float_as_uint(sA2[r + 4]);
                a[1][3] = __float_as_uint(sA2[r + 8 * ASTRIDE + 4]);
            }
#pragma unroll
            for (int g = 0; g < 2; g++)
#pragma unroll
                for (int nt = 0; nt < 8; nt++)
                    mma_tf32(acc[g][nt], a[g], b0[nt], b1[nt]);
        }
    }

    // Epilogue: out[8192, 512]; matrix g at column offset g*256
#pragma unroll
    for (int g = 0; g < 2; g++) {
        const int colbase = g * DD + wn * 64 + 2 * tig;
        const int row = m0 + wm * 16 + gid;
#pragma unroll
        for (int nt = 0; nt < 8; nt++) {
            float* p0 = out + (size_t)row * (2 * DD) + colbase + nt * 8;
            float* p1 = p0 + 8 * (2 * DD);
            *reinterpret_cast<float2*>(p0) = make_float2(acc[g][nt][0], acc[g][nt][1]);
            *reinterpret_cast<float2*>(p1) = make_float2(acc[g][nt][2], acc[g][nt][3]);
        }
    }
}

extern "C" void kernel_launch(void* const* d_in, const int* in_sizes, int n_in,
                              void* d_out, int out_size) {
    const float* x  = nullptr;
    const float* a1 = nullptr;
    const float* a2 = nullptr;
    for (int i = 0; i < n_in; i++) {
        if (in_sizes[i] == NN * DD)  x  = (const float*)d_in[i];
        else if (!a1)                a1 = (const float*)d_in[i];
        else                         a2 = (const float*)d_in[i];
    }

    static bool attr_set = false;
    if (!attr_set) {
        cudaFuncSetAttribute(h2gcn_mma,
                             cudaFuncAttributeMaxDynamicSharedMemorySize, SMEM_BYTES);
        attr_set = true;
    }

    xprep<<<(NN * DD) / 256, 256>>>(x);
    h2gcn_mma<<<NN / BM, 512, SMEM_BYTES>>>(a1, a2, (float*)d_out);
}

// round 7
// speedup vs baseline: 1.0011x; 1.0011x over previous
#include <cuda_runtime.h>
#include <cstdint>

// out = concat(adj_t @ x, adj_t2 @ x), N=8192, D=256, fp32 via tf32 mma.sync.
// R7: fused CTA, 512 threads, warp tile 32M x 32N x both matrices
// (1:1 LDS:MMA ratio like R5, but 4 warps/SMSP), 3-stage cp.async pipeline.

constexpr int NN = 8192;
constexpr int DD = 256;
constexpr int BM = 64;
constexpr int BK = 32;
constexpr int NITER = NN / BK;            // 256
constexpr int STAGES = 3;
constexpr int ASTRIDE = 36;               // conflict-free A row stride
constexpr int BSTRIDE = 264;              // conflict-free B row stride
constexpr int A_ELE = BM * ASTRIDE;       // 2304 floats per matrix
constexpr int B_ELE = BK * BSTRIDE;       // 8448 floats
constexpr int STG_FLT = 2 * A_ELE + B_ELE;       // 13056
constexpr int SMEM_BYTES = STAGES * STG_FLT * 4; // 156672

__device__ float g_xt[(size_t)NN * DD];   // x pre-converted to tf32 (rna)

#define CP_ASYNC16(dst, src) \
    asm volatile("cp.async.cg.shared.global [%0], [%1], 16;" :: "r"(dst), "l"(src))

__device__ __forceinline__ uint32_t smem_u32(const void* p) {
    uint32_t a;
    asm("{ .reg .u64 t; cvta.to.shared.u64 t, %1; cvt.u32.u64 %0, t; }"
        : "=r"(a) : "l"(p));
    return a;
}

__device__ __forceinline__ void mma_tf32(float c[4], const uint32_t a[4],
                                         const uint32_t b0, const uint32_t b1) {
    asm volatile(
        "mma.sync.aligned.m16n8k8.row.col.f32.tf32.tf32.f32 "
        "{%0,%1,%2,%3}, {%4,%5,%6,%7}, {%8,%9}, {%0,%1,%2,%3};"
        : "+f"(c[0]), "+f"(c[1]), "+f"(c[2]), "+f"(c[3])
        : "r"(a[0]), "r"(a[1]), "r"(a[2]), "r"(a[3]), "r"(b0), "r"(b1));
}

__global__ void xprep(const float* __restrict__ x) {
    const int i = blockIdx.x * 256 + threadIdx.x;
    float v = x[i];
    uint32_t t;
    asm("cvt.rna.tf32.f32 %0, %1;" : "=r"(t) : "f"(v));
    g_xt[i] = __uint_as_float(t);
}

__global__ void __launch_bounds__(512, 1) h2gcn_mma(
    const float* __restrict__ adj1,
    const float* __restrict__ adj2,
    float* __restrict__ out)
{
    extern __shared__ float smf[];
    const uint32_t smb = smem_u32(smf);

    const int t    = threadIdx.x;
    const int wid  = t >> 5;
    const int lane = t & 31;
    const int m0   = blockIdx.x * BM;

    const int wm  = wid & 1;     // 2 warp rows (32 M each)
    const int wn  = wid >> 1;    // 8 warp cols (32 N each)
    const int gid = lane >> 2;
    const int tig = lane & 3;

    // ---- cp.async assignments (512 threads): 1 A1 + 1 A2 + 4 B chunks ----
    const char* a1ptr; const char* a2ptr; uint32_t adst0;
    {
        int row = t >> 3;            // 0..63
        int c   = t & 7;
        a1ptr = reinterpret_cast<const char*>(adj1 + (size_t)(m0 + row) * NN) + c * 16;
        a2ptr = reinterpret_cast<const char*>(adj2 + (size_t)(m0 + row) * NN) + c * 16;
        adst0 = (uint32_t)((row * ASTRIDE + c * 4) * 4);
    }
    const char* bptr[4];
    uint32_t    bdst[4];
#pragma unroll
    for (int j = 0; j < 4; j++) {
        int id  = t + 512 * j;
        int row = id >> 6;           // k in tile (0..31)
        int c   = id & 63;
        bptr[j] = reinterpret_cast<const char*>(g_xt + (size_t)row * DD) + c * 16;
        bdst[j] = (uint32_t)((2 * A_ELE + row * BSTRIDE + c * 4) * 4);
    }

    auto load_stage = [&](int buf) {
        const uint32_t sb = smb + (uint32_t)(buf * STG_FLT * 4);
        CP_ASYNC16(sb + adst0, a1ptr);              a1ptr += BK * 4;
        CP_ASYNC16(sb + A_ELE * 4 + adst0, a2ptr);  a2ptr += BK * 4;
#pragma unroll
        for (int j = 0; j < 4; j++) {
            CP_ASYNC16(sb + bdst[j], bptr[j]);
            bptr[j] += (size_t)BK * DD * 4;
        }
        asm volatile("cp.async.commit_group;");
    };

    float acc[2][2][4][4];   // [mat][mt][nt][i]: 32M x 32N per warp, both mats
#pragma unroll
    for (int g = 0; g < 2; g++)
#pragma unroll
        for (int mt = 0; mt < 2; mt++)
#pragma unroll
            for (int nt = 0; nt < 4; nt++)
#pragma unroll
                for (int i = 0; i < 4; i++) acc[g][mt][nt][i] = 0.0f;

    const int ar0 = (wm * 32 + gid) * ASTRIDE + tig;   // A frag base
    const int bc0 = wn * 32 + gid;                      // B frag column base

    load_stage(0);
    load_stage(1);

    int buf = 0;            // compute buffer index
    int pre = 2 % STAGES;   // next prefetch buffer index

    for (int it = 0; it < NITER; it++) {
        if (it + 1 < NITER)
            asm volatile("cp.async.wait_group 1;");   // stage `it` complete
        else
            asm volatile("cp.async.wait_group 0;");
        __syncthreads();
        if (it + 2 < NITER) {
            load_stage(pre);
            pre = (pre == STAGES - 1) ? 0 : pre + 1;
        }

        const float* sA1 = smf + buf * STG_FLT;
        const float* sA2 = sA1 + A_ELE;
        const float* sB  = sA1 + 2 * A_ELE;
        buf = (buf == STAGES - 1) ? 0 : buf + 1;

#pragma unroll
        for (int ks = 0; ks < 4; ks++) {
            const int k = ks * 8;
            uint32_t b0[4], b1[4];
#pragma unroll
            for (int nt = 0; nt < 4; nt++) {
                const int n = bc0 + nt * 8;
                b0[nt] = __float_as_uint(sB[(k + tig) * BSTRIDE + n]);
                b1[nt] = __float_as_uint(sB[(k + tig + 4) * BSTRIDE + n]);
            }
            uint32_t a[2][2][4];
#pragma unroll
            for (int mt = 0; mt < 2; mt++) {
                const int r = ar0 + mt * 16 * ASTRIDE + k;
                a[0][mt][0] = __float_as_uint(sA1[r]);
                a[0][mt][1] = __float_as_uint(sA1[r + 8 * ASTRIDE]);
                a[0][mt][2] = __float_as_uint(sA1[r + 4]);
                a[0][mt][3] = __float_as_uint(sA1[r + 8 * ASTRIDE + 4]);
                a[1][mt][0] = __float_as_uint(sA2[r]);
                a[1][mt][1] = __float_as_uint(sA2[r + 8 * ASTRIDE]);
                a[1][mt][2] = __float_as_uint(sA2[r + 4]);
                a[1][mt][3] = __float_as_uint(sA2[r + 8 * ASTRIDE + 4]);
            }
#pragma unroll
            for (int g = 0; g < 2; g++)
#pragma unroll
                for (int mt = 0; mt < 2; mt++)
#pragma unroll
                    for (int nt = 0; nt < 4; nt++)
                        mma_tf32(acc[g][mt][nt], a[g][mt], b0[nt], b1[nt]);
        }
    }

    // Epilogue: out[8192, 512]; matrix g at column offset g*256
#pragma unroll
    for (int g = 0; g < 2; g++) {
        const int colbase = g * DD + wn * 32 + 2 * tig;
#pragma unroll
        for (int mt = 0; mt < 2; mt++) {
            const int row = m0 + wm * 32 + mt * 16 + gid;
#pragma unroll
            for (int nt = 0; nt < 4; nt++) {
                float* p0 = out + (size_t)row * (2 * DD) + colbase + nt * 8;
                float* p1 = p0 + 8 * (2 * DD);
                *reinterpret_cast<float2*>(p0) = make_float2(acc[g][mt][nt][0], acc[g][mt][nt][1]);
                *reinterpret_cast<float2*>(p1) = make_float2(acc[g][mt][nt][2], acc[g][mt][nt][3]);
            }
        }
    }
}

extern "C" void kernel_launch(void* const* d_in, const int* in_sizes, int n_in,
                              void* d_out, int out_size) {
    const float* x  = nullptr;
    const float* a1 = nullptr;
    const float* a2 = nullptr;
    for (int i = 0; i < n_in; i++) {
        if (in_sizes[i] == NN * DD)  x  = (const float*)d_in[i];
        else if (!a1)                a1 = (const float*)d_in[i];
        else                         a2 = (const float*)d_in[i];
    }

    static bool attr_set = false;
    if (!attr_set) {
        cudaFuncSetAttribute(h2gcn_mma,
                             cudaFuncAttributeMaxDynamicSharedMemorySize, SMEM_BYTES);
        attr_set = true;
    }

    xprep<<<(NN * DD) / 256, 256>>>(x);
    h2gcn_mma<<<NN / BM, 512, SMEM_BYTES>>>(a1, a2, (float*)d_out);
}

// round 8
// speedup vs baseline: 1.0806x; 1.0794x over previous
#include <cuda_runtime.h>
#include <cstdint>

// out = concat(adj_t @ x, adj_t2 @ x), N=8192, D=256, fp32 via tf32 mma.sync.
// R8: anti-convoy — BK=64 (half the barriers), and each warp rotates its
// ks-phase start (offset 2*(wid>>2)) so the 4 warps of an SMSP are always in
// different LDS/MMA phases instead of bursting in lockstep after the barrier.

constexpr int NN = 8192;
constexpr int DD = 256;
constexpr int BM = 64;
constexpr int BK = 64;
constexpr int NITER = NN / BK;            // 128
constexpr int ASTRIDE = 68;               // 64 + 4 pad; 68 % 32 == 4 -> conflict-free
constexpr int BSTRIDE = 264;              // 264 % 32 == 8 -> conflict-free
constexpr int A_ELE = BM * ASTRIDE;       // 4352 floats per matrix
constexpr int B_ELE = BK * BSTRIDE;       // 16896 floats
constexpr int STG_FLT = 2 * A_ELE + B_ELE;    // 25600
constexpr int SMEM_BYTES = 2 * STG_FLT * 4;   // 204800

__device__ float g_xt[(size_t)NN * DD];   // x pre-converted to tf32 (rna)

#define CP_ASYNC16(dst, src) \
    asm volatile("cp.async.cg.shared.global [%0], [%1], 16;" :: "r"(dst), "l"(src))

__device__ __forceinline__ uint32_t smem_u32(const void* p) {
    uint32_t a;
    asm("{ .reg .u64 t; cvta.to.shared.u64 t, %1; cvt.u32.u64 %0, t; }"
        : "=r"(a) : "l"(p));
    return a;
}

__device__ __forceinline__ void mma_tf32(float c[4], const uint32_t a[4],
                                         const uint32_t b0, const uint32_t b1) {
    asm volatile(
        "mma.sync.aligned.m16n8k8.row.col.f32.tf32.tf32.f32 "
        "{%0,%1,%2,%3}, {%4,%5,%6,%7}, {%8,%9}, {%0,%1,%2,%3};"
        : "+f"(c[0]), "+f"(c[1]), "+f"(c[2]), "+f"(c[3])
        : "r"(a[0]), "r"(a[1]), "r"(a[2]), "r"(a[3]), "r"(b0), "r"(b1));
}

__global__ void xprep(const float* __restrict__ x) {
    const int i = blockIdx.x * 256 + threadIdx.x;
    float v = x[i];
    uint32_t t;
    asm("cvt.rna.tf32.f32 %0, %1;" : "=r"(t) : "f"(v));
    g_xt[i] = __uint_as_float(t);
}

__global__ void __launch_bounds__(512, 1) h2gcn_mma(
    const float* __restrict__ adj1,
    const float* __restrict__ adj2,
    float* __restrict__ out)
{
    extern __shared__ float smf[];
    const uint32_t smb = smem_u32(smf);

    const int t    = threadIdx.x;
    const int wid  = t >> 5;
    const int lane = t & 31;
    const int m0   = blockIdx.x * BM;

    const int wm  = wid & 1;     // 2 warp rows (32 M each)
    const int wn  = wid >> 1;    // 8 warp cols (32 N each)
    const int gid = lane >> 2;
    const int tig = lane & 3;
    const int koff = (wid >> 2) * 2;   // ks rotation: 0/2/4/6 per SMSP buddy group

    // ---- cp.async assignments (512 threads, BK=64) ----
    // A1/A2: 64 rows x 16 chunks = 1024 each -> 2/thread; B: 4096 -> 8/thread
    const char* a1ptr[2]; const char* a2ptr[2]; uint32_t adst[2];
#pragma unroll
    for (int j = 0; j < 2; j++) {
        int id  = t + 512 * j;
        int row = id >> 4;           // 0..63
        int c   = id & 15;           // 16B chunk within 64-float row
        a1ptr[j] = reinterpret_cast<const char*>(adj1 + (size_t)(m0 + row) * NN) + c * 16;
        a2ptr[j] = reinterpret_cast<const char*>(adj2 + (size_t)(m0 + row) * NN) + c * 16;
        adst[j] = (uint32_t)((row * ASTRIDE + c * 4) * 4);
    }
    const char* bptr[8];
    uint32_t    bdst[8];
#pragma unroll
    for (int j = 0; j < 8; j++) {
        int id  = t + 512 * j;
        int row = id >> 6;           // k in tile (0..63)
        int c   = id & 63;
        bptr[j] = reinterpret_cast<const char*>(g_xt + (size_t)row * DD) + c * 16;
        bdst[j] = (uint32_t)((2 * A_ELE + row * BSTRIDE + c * 4) * 4);
    }

    auto load_stage = [&](int buf) {
        const uint32_t sb = smb + (uint32_t)(buf * STG_FLT * 4);
#pragma unroll
        for (int j = 0; j < 2; j++) {
            CP_ASYNC16(sb + adst[j], a1ptr[j]);              a1ptr[j] += BK * 4;
            CP_ASYNC16(sb + A_ELE * 4 + adst[j], a2ptr[j]);  a2ptr[j] += BK * 4;
        }
#pragma unroll
        for (int j = 0; j < 8; j++) {
            CP_ASYNC16(sb + bdst[j], bptr[j]);
            bptr[j] += (size_t)BK * DD * 4;
        }
        asm volatile("cp.async.commit_group;");
    };

    float acc[2][2][4][4];   // [mat][mt][nt][i]: 32M x 32N per warp, both mats
#pragma unroll
    for (int g = 0; g < 2; g++)
#pragma unroll
        for (int mt = 0; mt < 2; mt++)
#pragma unroll
            for (int nt = 0; nt < 4; nt++)
#pragma unroll
                for (int i = 0; i < 4; i++) acc[g][mt][nt][i] = 0.0f;

    const int ar0 = (wm * 32 + gid) * ASTRIDE + tig;   // A frag base
    const int bc0 = wn * 32 + gid;                      // B frag column base

    load_stage(0);

    for (int it = 0; it < NITER; it++) {
        asm volatile("cp.async.wait_group 0;");
        __syncthreads();
        if (it + 1 < NITER) load_stage((it + 1) & 1);

        const float* sA1 = smf + (it & 1) * STG_FLT;
        const float* sA2 = sA1 + A_ELE;
        const float* sB  = sA1 + 2 * A_ELE;

#pragma unroll
        for (int ks = 0; ks < 8; ks++) {
            const int k = ((ks + koff) & 7) * 8;     // warp-private phase rotation
            uint32_t b0[4], b1[4];
#pragma unroll
            for (int nt = 0; nt < 4; nt++) {
                const int n = bc0 + nt * 8;
                b0[nt] = __float_as_uint(sB[(k + tig) * BSTRIDE + n]);
                b1[nt] = __float_as_uint(sB[(k + tig + 4) * BSTRIDE + n]);
            }
            uint32_t a[2][2][4];
#pragma unroll
            for (int mt = 0; mt < 2; mt++) {
                const int r = ar0 + mt * 16 * ASTRIDE + k;
                a[0][mt][0] = __float_as_uint(sA1[r]);
                a[0][mt][1] = __float_as_uint(sA1[r + 8 * ASTRIDE]);
                a[0][mt][2] = __float_as_uint(sA1[r + 4]);
                a[0][mt][3] = __float_as_uint(sA1[r + 8 * ASTRIDE + 4]);
                a[1][mt][0] = __float_as_uint(sA2[r]);
                a[1][mt][1] = __float_as_uint(sA2[r + 8 * ASTRIDE]);
                a[1][mt][2] = __float_as_uint(sA2[r + 4]);
                a[1][mt][3] = __float_as_uint(sA2[r + 8 * ASTRIDE + 4]);
            }
#pragma unroll
            for (int g = 0; g < 2; g++)
#pragma unroll
                for (int mt = 0; mt < 2; mt++)
#pragma unroll
                    for (int nt = 0; nt < 4; nt++)
                        mma_tf32(acc[g][mt][nt], a[g][mt], b0[nt], b1[nt]);
        }
    }

    // Epilogue: out[8192, 512]; matrix g at column offset g*256
#pragma unroll
    for (int g = 0; g < 2; g++) {
        const int colbase = g * DD + wn * 32 + 2 * tig;
#pragma unroll
        for (int mt = 0; mt < 2; mt++) {
            const int row = m0 + wm * 32 + mt * 16 + gid;
#pragma unroll
            for (int nt = 0; nt < 4; nt++) {
                float* p0 = out + (size_t)row * (2 * DD) + colbase + nt * 8;
                float* p1 = p0 + 8 * (2 * DD);
                *reinterpret_cast<float2*>(p0) = make_float2(acc[g][mt][nt][0], acc[g][mt][nt][1]);
                *reinterpret_cast<float2*>(p1) = make_float2(acc[g][mt][nt][2], acc[g][mt][nt][3]);
            }
        }
    }
}

extern "C" void kernel_launch(void* const* d_in, const int* in_sizes, int n_in,
                              void* d_out, int out_size) {
    const float* x  = nullptr;
    const float* a1 = nullptr;
    const float* a2 = nullptr;
    for (int i = 0; i < n_in; i++) {
        if (in_sizes[i] == NN * DD)  x  = (const float*)d_in[i];
        else if (!a1)                a1 = (const float*)d_in[i];
        else                         a2 = (const float*)d_in[i];
    }

    static bool attr_set = false;
    if (!attr_set) {
        cudaFuncSetAttribute(h2gcn_mma,
                             cudaFuncAttributeMaxDynamicSharedMemorySize, SMEM_BYTES);
        attr_set = true;
    }

    xprep<<<(NN * DD) / 256, 256>>>(x);
    h2gcn_mma<<<NN / BM, 512, SMEM_BYTES>>>(a1, a2, (float*)d_out);
}

// round 9
// speedup vs baseline: 1.1106x; 1.0278x over previous
#include <cuda_runtime.h>
#include <cstdint>

// out = concat(adj_t @ x, adj_t2 @ x), N=8192, D=256, fp32 via tf32 mma.sync.
// R9: 8 warps (Mw=32, Nw=64, both mats => 1:1 LDS:MMA byte ratio, crossbar
// ~70% of tensor floor) + BK=64 + per-warp ks rotation so the 2 warps per
// SMSP run anti-phased (LDS burst under MMA burst).

constexpr int NN = 8192;
constexpr int DD = 256;
constexpr int BM = 64;
constexpr int BK = 64;
constexpr int NITER = NN / BK;            // 128
constexpr int ASTRIDE = 68;               // 68 % 32 == 4 -> conflict-free scalar A
constexpr int BSTRIDE = 264;              // 264 % 32 == 8 -> conflict-free B
constexpr int A_ELE = BM * ASTRIDE;       // 4352 floats per matrix
constexpr int B_ELE = BK * BSTRIDE;       // 16896 floats
constexpr int STG_FLT = 2 * A_ELE + B_ELE;    // 25600
constexpr int SMEM_BYTES = 2 * STG_FLT * 4;   // 204800

__device__ float g_xt[(size_t)NN * DD];   // x pre-converted to tf32 (rna)

#define CP_ASYNC16(dst, src) \
    asm volatile("cp.async.cg.shared.global [%0], [%1], 16;" :: "r"(dst), "l"(src))

__device__ __forceinline__ uint32_t smem_u32(const void* p) {
    uint32_t a;
    asm("{ .reg .u64 t; cvta.to.shared.u64 t, %1; cvt.u32.u64 %0, t; }"
        : "=r"(a) : "l"(p));
    return a;
}

__device__ __forceinline__ void mma_tf32(float c[4], const uint32_t a[4],
                                         const uint32_t b0, const uint32_t b1) {
    asm volatile(
        "mma.sync.aligned.m16n8k8.row.col.f32.tf32.tf32.f32 "
        "{%0,%1,%2,%3}, {%4,%5,%6,%7}, {%8,%9}, {%0,%1,%2,%3};"
        : "+f"(c[0]), "+f"(c[1]), "+f"(c[2]), "+f"(c[3])
        : "r"(a[0]), "r"(a[1]), "r"(a[2]), "r"(a[3]), "r"(b0), "r"(b1));
}

__global__ void xprep(const float* __restrict__ x) {
    const int i = blockIdx.x * 256 + threadIdx.x;
    float v = x[i];
    uint32_t t;
    asm("cvt.rna.tf32.f32 %0, %1;" : "=r"(t) : "f"(v));
    g_xt[i] = __uint_as_float(t);
}

__global__ void __launch_bounds__(256, 1) h2gcn_mma(
    const float* __restrict__ adj1,
    const float* __restrict__ adj2,
    float* __restrict__ out)
{
    extern __shared__ float smf[];
    const uint32_t smb = smem_u32(smf);

    const int t    = threadIdx.x;
    const int wid  = t >> 5;
    const int lane = t & 31;
    const int m0   = blockIdx.x * BM;

    const int wm  = wid & 1;         // 2 warp rows (32 M each)
    const int wn  = wid >> 1;        // 4 warp cols (64 N each)
    const int gid = lane >> 2;
    const int tig = lane & 3;
    const int koff = (wid >> 2) * 4; // anti-phase: warps wid and wid+4 share an SMSP

    // ---- cp.async assignments (256 threads, BK=64) ----
    // A1/A2: 64 rows x 16 chunks = 1024 each -> 4/thread; B: 4096 -> 16/thread
    const char* a1ptr[4]; const char* a2ptr[4]; uint32_t adst[4];
#pragma unroll
    for (int j = 0; j < 4; j++) {
        int id  = t + 256 * j;
        int row = id >> 4;           // 0..63
        int c   = id & 15;           // 16B chunk within 64-float row
        a1ptr[j] = reinterpret_cast<const char*>(adj1 + (size_t)(m0 + row) * NN) + c * 16;
        a2ptr[j] = reinterpret_cast<const char*>(adj2 + (size_t)(m0 + row) * NN) + c * 16;
        adst[j] = (uint32_t)((row * ASTRIDE + c * 4) * 4);
    }
    const char* bptr[16];
    uint32_t    bdst[16];
#pragma unroll
    for (int j = 0; j < 16; j++) {
        int id  = t + 256 * j;
        int row = id >> 6;           // k in tile (0..63)
        int c   = id & 63;
        bptr[j] = reinterpret_cast<const char*>(g_xt + (size_t)row * DD) + c * 16;
        bdst[j] = (uint32_t)((2 * A_ELE + row * BSTRIDE + c * 4) * 4);
    }

    auto load_stage = [&](int buf) {
        const uint32_t sb = smb + (uint32_t)(buf * STG_FLT * 4);
#pragma unroll
        for (int j = 0; j < 4; j++) {
            CP_ASYNC16(sb + adst[j], a1ptr[j]);              a1ptr[j] += BK * 4;
            CP_ASYNC16(sb + A_ELE * 4 + adst[j], a2ptr[j]);  a2ptr[j] += BK * 4;
        }
#pragma unroll
        for (int j = 0; j < 16; j++) {
            CP_ASYNC16(sb + bdst[j], bptr[j]);
            bptr[j] += (size_t)BK * DD * 4;
        }
        asm volatile("cp.async.commit_group;");
    };

    float acc[2][2][8][4];   // [mat][mt][nt][i]: 32M x 64N per warp, both mats
#pragma unroll
    for (int g = 0; g < 2; g++)
#pragma unroll
        for (int mt = 0; mt < 2; mt++)
#pragma unroll
            for (int nt = 0; nt < 8; nt++)
#pragma unroll
                for (int i = 0; i < 4; i++) acc[g][mt][nt][i] = 0.0f;

    const int ar0 = (wm * 32 + gid) * ASTRIDE + tig;   // A frag base
    const int bc0 = wn * 64 + gid;                      // B frag column base

    load_stage(0);

    for (int it = 0; it < NITER; it++) {
        asm volatile("cp.async.wait_group 0;");
        __syncthreads();
        if (it + 1 < NITER) load_stage((it + 1) & 1);

        const float* sA1 = smf + (it & 1) * STG_FLT;
        const float* sA2 = sA1 + A_ELE;
        const float* sB  = sA1 + 2 * A_ELE;

#pragma unroll
        for (int ks = 0; ks < 8; ks++) {
            const int k = ((ks + koff) & 7) * 8;   // warp-private phase rotation
            uint32_t b0[8], b1[8];
#pragma unroll
            for (int nt = 0; nt < 8; nt++) {
                const int n = bc0 + nt * 8;
                b0[nt] = __float_as_uint(sB[(k + tig) * BSTRIDE + n]);
                b1[nt] = __float_as_uint(sB[(k + tig + 4) * BSTRIDE + n]);
            }
            uint32_t a[2][2][4];
#pragma unroll
            for (int mt = 0; mt < 2; mt++) {
                const int r = ar0 + mt * 16 * ASTRIDE + k;
                a[0][mt][0] = __float_as_uint(sA1[r]);
                a[0][mt][1] = __float_as_uint(sA1[r + 8 * ASTRIDE]);
                a[0][mt][2] = __float_as_uint(sA1[r + 4]);
                a[0][mt][3] = __float_as_uint(sA1[r + 8 * ASTRIDE + 4]);
                a[1][mt][0] = __float_as_uint(sA2[r]);
                a[1][mt][1] = __float_as_uint(sA2[r + 8 * ASTRIDE]);
                a[1][mt][2] = __float_as_uint(sA2[r + 4]);
                a[1][mt][3] = __float_as_uint(sA2[r + 8 * ASTRIDE + 4]);
            }
#pragma unroll
            for (int g = 0; g < 2; g++)
#pragma unroll
                for (int mt = 0; mt < 2; mt++)
#pragma unroll
                    for (int nt = 0; nt < 8; nt++)
                        mma_tf32(acc[g][mt][nt], a[g][mt], b0[nt], b1[nt]);
        }
    }

    // Epilogue: out[8192, 512]; matrix g at column offset g*256
#pragma unroll
    for (int g = 0; g < 2; g++) {
        const int colbase = g * DD + wn * 64 + 2 * tig;
#pragma unroll
        for (int mt = 0; mt < 2; mt++) {
            const int row = m0 + wm * 32 + mt * 16 + gid;
#pragma unroll
            for (int nt = 0; nt < 8; nt++) {
                float* p0 = out + (size_t)row * (2 * DD) + colbase + nt * 8;
                float* p1 = p0 + 8 * (2 * DD);
                *reinterpret_cast<float2*>(p0) = make_float2(acc[g][mt][nt][0], acc[g][mt][nt][1]);
                *reinterpret_cast<float2*>(p1) = make_float2(acc[g][mt][nt][2], acc[g][mt][nt][3]);
            }
        }
    }
}

extern "C" void kernel_launch(void* const* d_in, const int* in_sizes, int n_in,
                              void* d_out, int out_size) {
    const float* x  = nullptr;
    const float* a1 = nullptr;
    const float* a2 = nullptr;
    for (int i = 0; i < n_in; i++) {
        if (in_sizes[i] == NN * DD)  x  = (const float*)d_in[i];
        else if (!a1)                a1 = (const float*)d_in[i];
        else                         a2 = (const float*)d_in[i];
    }

    static bool attr_set = false;
    if (!attr_set) {
        cudaFuncSetAttribute(h2gcn_mma,
                             cudaFuncAttributeMaxDynamicSharedMemorySize, SMEM_BYTES);
        attr_set = true;
    }

    xprep<<<(NN * DD) / 256, 256>>>(x);
    h2gcn_mma<<<NN / BM, 256, SMEM_BYTES>>>(a1, a2, (float*)d_out);
}